// round 1
// baseline (speedup 1.0000x reference)
#include <cuda_runtime.h>

// PEquiNN: o_x = l_xx*X + (g_xx*rowsum(X) + g_yx*rowsum(Y)) broadcast per row
//          o_y = l_yy*Y + (g_yy*rowsum(Y) + g_xy*rowsum(X)) broadcast per row
// X, Y: [R, N] f32 with N = 4096, R = 8192. Pure streaming: read 256 MiB,
// write 256 MiB, one pass (row data held in registers across the reduction).

#define N_COLS 4096
#define VEC_PER_ROW (N_COLS / 4)   // 1024 float4 per row
#define THREADS 256
#define V_PER_THREAD (VEC_PER_ROW / THREADS)  // 4 float4 = 16 floats per thread

__global__ __launch_bounds__(THREADS)
void peq_kernel(const float4* __restrict__ X,
                const float4* __restrict__ Y,
                const float* __restrict__ p_lxx,
                const float* __restrict__ p_lyy,
                const float* __restrict__ p_gxx,
                const float* __restrict__ p_gxy,
                const float* __restrict__ p_gyx,
                const float* __restrict__ p_gyy,
                float4* __restrict__ OX,
                float4* __restrict__ OY)
{
    const int row = blockIdx.x;
    const size_t base = (size_t)row * VEC_PER_ROW;
    const int tid = threadIdx.x;

    // Load the full row (X and Y) into registers; accumulate partial sums.
    float4 xv[V_PER_THREAD];
    float4 yv[V_PER_THREAD];
    float sx = 0.f, sy = 0.f;
#pragma unroll
    for (int i = 0; i < V_PER_THREAD; i++) {
        xv[i] = X[base + tid + i * THREADS];
        yv[i] = Y[base + tid + i * THREADS];
        sx += (xv[i].x + xv[i].y) + (xv[i].z + xv[i].w);
        sy += (yv[i].x + yv[i].y) + (yv[i].z + yv[i].w);
    }

    // Warp reduce both sums.
#pragma unroll
    for (int o = 16; o > 0; o >>= 1) {
        sx += __shfl_xor_sync(0xFFFFFFFFu, sx, o);
        sy += __shfl_xor_sync(0xFFFFFFFFu, sy, o);
    }

    // Cross-warp reduce (8 warps).
    __shared__ float ssx[THREADS / 32];
    __shared__ float ssy[THREADS / 32];
    const int wid = tid >> 5;
    const int lid = tid & 31;
    if (lid == 0) { ssx[wid] = sx; ssy[wid] = sy; }
    __syncthreads();
    sx = 0.f; sy = 0.f;
#pragma unroll
    for (int i = 0; i < THREADS / 32; i++) { sx += ssx[i]; sy += ssy[i]; }

    // Scalars (uniform loads, L2/L1 cached after first CTA).
    const float lxx = __ldg(p_lxx);
    const float lyy = __ldg(p_lyy);
    const float gxx = __ldg(p_gxx);
    const float gxy = __ldg(p_gxy);
    const float gyx = __ldg(p_gyx);
    const float gyy = __ldg(p_gyy);

    const float bx = gxx * sx + gyx * sy;  // broadcast term for o_x row
    const float by = gyy * sy + gxy * sx;  // broadcast term for o_y row

#pragma unroll
    for (int i = 0; i < V_PER_THREAD; i++) {
        float4 ox, oy;
        ox.x = fmaf(lxx, xv[i].x, bx);
        ox.y = fmaf(lxx, xv[i].y, bx);
        ox.z = fmaf(lxx, xv[i].z, bx);
        ox.w = fmaf(lxx, xv[i].w, bx);
        oy.x = fmaf(lyy, yv[i].x, by);
        oy.y = fmaf(lyy, yv[i].y, by);
        oy.z = fmaf(lyy, yv[i].z, by);
        oy.w = fmaf(lyy, yv[i].w, by);
        OX[base + tid + i * THREADS] = ox;
        OY[base + tid + i * THREADS] = oy;
    }
}

extern "C" void kernel_launch(void* const* d_in, const int* in_sizes, int n_in,
                              void* d_out, int out_size)
{
    const float4* X = (const float4*)d_in[0];
    const float4* Y = (const float4*)d_in[1];
    const float* lxx = (const float*)d_in[2];
    const float* lyy = (const float*)d_in[3];
    const float* gxx = (const float*)d_in[4];
    const float* gxy = (const float*)d_in[5];
    const float* gyx = (const float*)d_in[6];
    const float* gyy = (const float*)d_in[7];

    const int total = in_sizes[0];          // R * N
    const int rows = total / N_COLS;        // 8192

    float* out = (float*)d_out;
    float4* OX = (float4*)out;                          // o_x first
    float4* OY = (float4*)(out + (size_t)total);        // o_y second

    peq_kernel<<<rows, THREADS>>>(X, Y, lxx, lyy, gxx, gxy, gyx, gyy, OX, OY);
}

// round 2
// speedup vs baseline: 1.0086x; 1.0086x over previous
#include <cuda_runtime.h>

// PEquiNN: o_x = l_xx*X + (g_xx*rowsum(X) + g_yx*rowsum(Y)) per row
//          o_y = l_yy*Y + (g_yy*rowsum(Y) + g_xy*rowsum(X)) per row
// X, Y: [8192, 4096] f32. Single-pass streaming: 256 MiB read + 256 MiB write.
//
// R2: split-block layout. 512 threads/CTA: warps 0-7 hold the X row, warps
// 8-15 hold the Y row (4 float4 each => ~30 regs/thread => ~100% occupancy).
// Joint row-sum via shared memory. Streaming cache hints (ldcs/stcs) since
// every byte is touched exactly once.

#define N_COLS 4096
#define VEC_PER_ROW (N_COLS / 4)       // 1024 float4 per row
#define THREADS 512
#define HALF 256                        // threads per matrix half
#define V_PER_THREAD (VEC_PER_ROW / HALF)  // 4 float4 = 16 floats per thread

__global__ __launch_bounds__(THREADS)
void peq_kernel(const float4* __restrict__ X,
                const float4* __restrict__ Y,
                const float* __restrict__ p_lxx,
                const float* __restrict__ p_lyy,
                const float* __restrict__ p_gxx,
                const float* __restrict__ p_gxy,
                const float* __restrict__ p_gyx,
                const float* __restrict__ p_gyy,
                float4* __restrict__ OX,
                float4* __restrict__ OY)
{
    const int row = blockIdx.x;
    const size_t base = (size_t)row * VEC_PER_ROW;
    const int tid = threadIdx.x;
    const int half_tid = tid & (HALF - 1);   // 0..255 within the half
    const bool is_y = tid >= HALF;           // warps 8-15 handle Y

    const float4* __restrict__ SRC = is_y ? Y : X;

    // Load this half-row into registers; accumulate partial sum.
    float4 v[V_PER_THREAD];
    float s = 0.f;
#pragma unroll
    for (int i = 0; i < V_PER_THREAD; i++) {
        v[i] = __ldcs(&SRC[base + half_tid + i * HALF]);
        s += (v[i].x + v[i].y) + (v[i].z + v[i].w);
    }

    // Warp reduce.
#pragma unroll
    for (int o = 16; o > 0; o >>= 1)
        s += __shfl_xor_sync(0xFFFFFFFFu, s, o);

    // Cross-warp: warps 0-7 carry X partials, warps 8-15 carry Y partials.
    __shared__ float ssum[THREADS / 32];     // 16 entries
    const int wid = tid >> 5;
    if ((tid & 31) == 0) ssum[wid] = s;
    __syncthreads();

    float sx = 0.f, sy = 0.f;
#pragma unroll
    for (int i = 0; i < 8; i++)  sx += ssum[i];
#pragma unroll
    for (int i = 8; i < 16; i++) sy += ssum[i];

    const float lxx = __ldg(p_lxx);
    const float lyy = __ldg(p_lyy);
    const float gxx = __ldg(p_gxx);
    const float gxy = __ldg(p_gxy);
    const float gyx = __ldg(p_gyx);
    const float gyy = __ldg(p_gyy);

    // Per-half diagonal scale + broadcast term.
    const float l = is_y ? lyy : lxx;
    const float b = is_y ? (gyy * sy + gxy * sx)    // o_y broadcast
                         : (gxx * sx + gyx * sy);   // o_x broadcast

    float4* __restrict__ DST = is_y ? OY : OX;

#pragma unroll
    for (int i = 0; i < V_PER_THREAD; i++) {
        float4 o;
        o.x = fmaf(l, v[i].x, b);
        o.y = fmaf(l, v[i].y, b);
        o.z = fmaf(l, v[i].z, b);
        o.w = fmaf(l, v[i].w, b);
        __stcs(&DST[base + half_tid + i * HALF], o);
    }
}

extern "C" void kernel_launch(void* const* d_in, const int* in_sizes, int n_in,
                              void* d_out, int out_size)
{
    const float4* X = (const float4*)d_in[0];
    const float4* Y = (const float4*)d_in[1];
    const float* lxx = (const float*)d_in[2];
    const float* lyy = (const float*)d_in[3];
    const float* gxx = (const float*)d_in[4];
    const float* gxy = (const float*)d_in[5];
    const float* gyx = (const float*)d_in[6];
    const float* gyy = (const float*)d_in[7];

    const int total = in_sizes[0];          // R * N = 8192 * 4096
    const int rows = total / N_COLS;        // 8192

    float* out = (float*)d_out;
    float4* OX = (float4*)out;                          // o_x first
    float4* OY = (float4*)(out + (size_t)total);        // o_y second

    peq_kernel<<<rows, THREADS>>>(X, Y, lxx, lyy, gxx, gxy, gyx, gyy, OX, OY);
}